// round 2
// baseline (speedup 1.0000x reference)
#include <cuda_runtime.h>
#include <math.h>

#define NB 64
#define NS 1024
#define NF 128
#define NK 64
#define BSROWS (NB*NS)

// ---------------- scratch (allocation-free: __device__ globals) ----------------
__device__ float g_p1[BSROWS*NF];      // pairsum(f1)  [B,S,F]
__device__ float g_p2[BSROWS*NF];      // pairsum(f2)
__device__ float g_G [BSROWS*NF];      // G gate       [B,S,F]
__device__ float g_M [NB*NF*NS];       // M = x^T A    [B,F,S]   (reused per modality)
__device__ float g_C [NB*NF*2*NF];     // C tile       [B,F,2F]
__device__ float g_H [NB*NF*NK];       // H            [B,F,K]
__device__ float g_ss[4];              // sumsq(f1),sumsq(f2),sumsq(f3)
__device__ float g_w [4];              // w1, w2, 2*c3
__device__ float g_cn[NB*NF];          // per-(b,f) sumsq of z over s

// ---------------- small kernels ----------------
__global__ void zero_kernel() {
    int i = blockIdx.x * blockDim.x + threadIdx.x;
    if (i < 4) g_ss[i] = 0.f;
    if (i < NB*NF) g_cn[i] = 0.f;
}

__global__ void scalars_kernel() {
    float n1 = sqrtf(g_ss[0]), n2 = sqrtf(g_ss[1]), n3 = sqrtf(g_ss[2]);
    g_w[0] = n1 / (n1 + n2);
    g_w[1] = n2 / (n1 + n2);
    g_w[2] = 2.f * n3 * n3 / (n1 + n2 + n3);   // pair-sum of scalar term
}

// partial sumsq of z over s, per (b,f)
__global__ void colnorm_kernel() {
    int b = blockIdx.x, c = blockIdx.y, f = threadIdx.x;
    float w1 = g_w[0], w2 = g_w[1], cc = g_w[2];
    float s = 0.f;
    int base = (b*NS + c*32)*NF + f;
    #pragma unroll 4
    for (int i = 0; i < 32; ++i) {
        float z = w1*g_p1[base + i*NF] + w2*g_p2[base + i*NF] + cc;
        s += z*z;
    }
    atomicAdd(&g_cn[b*NF + f], s);
}

__global__ void gwrite_kernel() {
    int idx = blockIdx.x * blockDim.x + threadIdx.x;
    if (idx >= BSROWS*NF) return;
    int f = idx & (NF - 1);
    int b = idx / (NS*NF);
    float z = g_w[0]*g_p1[idx] + g_w[1]*g_p2[idx] + g_w[2];
    float n = fmaxf(sqrtf(g_cn[b*NF + f]), 1e-12f);
    g_G[idx] = z / n;
}

// ---------------- generic tiled SGEMM with fused epilogues ----------------
// C[b,m,n] = sum_k Aop(b,m,k) * Bop(b,n,k)
//   TA=false: A[m*lda+k]   TA=true: A[k*lda+m]
//   TB=false: B[n*ldb+k]   TB=true: B[k*ldb+n]
// EPI: 0 plain store | 1 +bias, pairsum->aux, sumsq->ssum | 2 +bias, sumsq only
//      3 tanh(acc/16) | 4 relu(acc + aux) | 5 acc + aux (residual)
template<int BM, int BN, int BK, int TM, int TN, bool TA, bool TB, int EPI>
__global__ __launch_bounds__(256)
void gemm_kernel(const float* __restrict__ A, const float* __restrict__ Bp,
                 float* __restrict__ C, int K,
                 int lda, int ldb, int ldc,
                 long long bsA, long long bsB, long long bsC,
                 const float* __restrict__ bias,
                 float* __restrict__ aux, int ldaux, long long bsAux,
                 float* __restrict__ ssum)
{
    constexpr int TPB = (BM/TM) * (BN/TN);   // 256
    __shared__ float As[BK][BM + 4];
    __shared__ float Bs[BK][BN + 4];
    __shared__ float red[TPB/32];

    const int tid = threadIdx.x;
    const int bz  = blockIdx.z;
    const int m0  = blockIdx.x * BM;
    const int n0  = blockIdx.y * BN;
    const float* Ab = A  + (long long)bz * bsA;
    const float* Bb = Bp + (long long)bz * bsB;

    const int tr = tid / (BN/TN);
    const int tc = tid % (BN/TN);

    float acc[TM][TN];
    #pragma unroll
    for (int i = 0; i < TM; ++i)
        #pragma unroll
        for (int j = 0; j < TN; ++j) acc[i][j] = 0.f;

    for (int k0 = 0; k0 < K; k0 += BK) {
        #pragma unroll
        for (int t = 0; t < (BM*BK)/TPB; ++t) {
            int idx = tid + t*TPB;
            if (TA) { int k = idx / BM, m = idx % BM;
                As[k][m] = Ab[(long long)(k0 + k)*lda + (m0 + m)];
            } else   { int m = idx / BK, k = idx % BK;
                As[k][m] = Ab[(long long)(m0 + m)*lda + (k0 + k)];
            }
        }
        #pragma unroll
        for (int t = 0; t < (BN*BK)/TPB; ++t) {
            int idx = tid + t*TPB;
            if (TB) { int k = idx / BN, n = idx % BN;
                Bs[k][n] = Bb[(long long)(k0 + k)*ldb + (n0 + n)];
            } else   { int n = idx / BK, k = idx % BK;
                Bs[k][n] = Bb[(long long)(n0 + n)*ldb + (k0 + k)];
            }
        }
        __syncthreads();
        #pragma unroll
        for (int kk = 0; kk < BK; ++kk) {
            float a[TM], b[TN];
            #pragma unroll
            for (int i = 0; i < TM; ++i) a[i] = As[kk][tr*TM + i];
            #pragma unroll
            for (int j = 0; j < TN; ++j) b[j] = Bs[kk][tc*TN + j];
            #pragma unroll
            for (int i = 0; i < TM; ++i)
                #pragma unroll
                for (int j = 0; j < TN; ++j)
                    acc[i][j] = fmaf(a[i], b[j], acc[i][j]);
        }
        __syncthreads();
    }

    const int rm = m0 + tr*TM;
    const int cn = n0 + tc*TN;

    if (EPI == 0) {
        float* Cb = C + (long long)bz * bsC;
        #pragma unroll
        for (int i = 0; i < TM; ++i)
            #pragma unroll
            for (int j = 0; j < TN; ++j)
                Cb[(long long)(rm + i)*ldc + (cn + j)] = acc[i][j];
    } else if (EPI == 1 || EPI == 2) {
        float local = 0.f;
        #pragma unroll
        for (int i = 0; i < TM; ++i)
            #pragma unroll
            for (int j = 0; j < TN; ++j) {
                float v = acc[i][j] + bias[cn + j];
                acc[i][j] = v;
                local += v * v;
            }
        if (EPI == 1) {
            float* Pb = aux + (long long)bz * bsAux;
            #pragma unroll
            for (int i = 0; i < TM; ++i)
                #pragma unroll
                for (int j = 0; j < TN; j += 2)
                    Pb[(long long)(rm + i)*ldaux + (cn + j)/2] = acc[i][j] + acc[i][j+1];
        }
        #pragma unroll
        for (int o = 16; o; o >>= 1) local += __shfl_down_sync(0xffffffffu, local, o);
        int w = tid >> 5, l = tid & 31;
        if (l == 0) red[w] = local;
        __syncthreads();
        if (tid == 0) {
            float t = 0.f;
            #pragma unroll
            for (int i = 0; i < TPB/32; ++i) t += red[i];
            atomicAdd(ssum, t);
        }
    } else if (EPI == 3) {
        float* Cb = C + (long long)bz * bsC;
        #pragma unroll
        for (int i = 0; i < TM; ++i)
            #pragma unroll
            for (int j = 0; j < TN; ++j)
                Cb[(long long)(rm + i)*ldc + (cn + j)] = tanhf(acc[i][j] * 0.0625f);
    } else if (EPI == 4) {
        float* Cb = C + (long long)bz * bsC;
        const float* Xb = aux + (long long)bz * bsAux;
        #pragma unroll
        for (int i = 0; i < TM; ++i)
            #pragma unroll
            for (int j = 0; j < TN; ++j) {
                float v = acc[i][j] + Xb[(long long)(rm + i)*ldaux + (cn + j)];
                Cb[(long long)(rm + i)*ldc + (cn + j)] = fmaxf(v, 0.f);
            }
    } else if (EPI == 5) {
        float* Cb = C + (long long)bz * bsC;
        const float* Xb = aux + (long long)bz * bsAux;
        #pragma unroll
        for (int i = 0; i < TM; ++i)
            #pragma unroll
            for (int j = 0; j < TN; ++j)
                Cb[(long long)(rm + i)*ldc + (cn + j)] =
                    acc[i][j] + Xb[(long long)(rm + i)*ldaux + (cn + j)];
    }
}

// ---------------- launcher ----------------
extern "C" void kernel_launch(void* const* d_in, const int* in_sizes, int n_in,
                              void* d_out, int out_size)
{
    const float* txt = (const float*)d_in[0];   // f1_norm
    const float* aud = (const float*)d_in[1];   // f2_norm
    const float* vis = (const float*)d_in[2];   // f3_norm
    const float* Wi  = (const float*)d_in[3];
    const float* bi  = (const float*)d_in[4];
    const float* Wq  = (const float*)d_in[5];
    const float* bq  = (const float*)d_in[6];
    const float* Wvp = (const float*)d_in[7];
    const float* bvp = (const float*)d_in[8];
    const float* Aa  = (const float*)d_in[9];
    const float* Av  = (const float*)d_in[10];
    const float* Al  = (const float*)d_in[11];
    const float* Wa  = (const float*)d_in[12];
    const float* Wv  = (const float*)d_in[13];
    const float* Wt  = (const float*)d_in[14];
    const float* Wca = (const float*)d_in[15];
    const float* Wcv = (const float*)d_in[16];
    const float* Wct = (const float*)d_in[17];
    const float* Wha = (const float*)d_in[18];
    const float* Whv = (const float*)d_in[19];
    const float* Wht = (const float*)d_in[20];
    float* out = (float*)d_out;

    float *p1, *p2, *G, *Mx, *Cx, *H, *ss;
    cudaGetSymbolAddress((void**)&p1, g_p1);
    cudaGetSymbolAddress((void**)&p2, g_p2);
    cudaGetSymbolAddress((void**)&G , g_G);
    cudaGetSymbolAddress((void**)&Mx, g_M);
    cudaGetSymbolAddress((void**)&Cx, g_C);
    cudaGetSymbolAddress((void**)&H , g_H);
    cudaGetSymbolAddress((void**)&ss, g_ss);

    dim3 blk(256);

    // zero accumulators (graph replays!)
    zero_kernel<<<32, 256>>>();

    // ---- AMLP projections: f_i = x @ W^T + b ; pairsum -> p ; sumsq -> ss ----
    gemm_kernel<128,128,8,8,8,false,false,1><<<dim3(BSROWS/128, 2, 1), blk>>>(
        txt, Wi, nullptr, NF, NF, NF, 0, 0, 0, 0, bi, p1, NF, 0, ss + 0);
    gemm_kernel<128,128,8,8,8,false,false,1><<<dim3(BSROWS/128, 2, 1), blk>>>(
        aud, Wq, nullptr, NF, NF, NF, 0, 0, 0, 0, bq, p2, NF, 0, ss + 1);
    gemm_kernel<128,128,8,8,8,false,false,2><<<dim3(BSROWS/128, 2, 1), blk>>>(
        vis, Wvp, nullptr, NF, NF, NF, 0, 0, 0, 0, bvp, nullptr, 0, 0, ss + 2);

    scalars_kernel<<<1, 1>>>();
    colnorm_kernel<<<dim3(NB, 32, 1), NF>>>();
    gwrite_kernel<<<(BSROWS*NF)/256, 256>>>();

    // ---- per-modality pipeline (output order: t, a, v) ----
    struct Mod { const float* x; const float* Amat; const float* clo;
                 const float* Wk; const float* Wc; const float* Wh; int slot; };
    Mod mods[3] = {
        { aud, Aa, aud, Wa, Wca, Wha, 1 },   // audio
        { vis, Av, aud, Wv, Wcv, Whv, 2 },   // visual (source bug: uses G_ag -> lo half = aud)
        { txt, Al, txt, Wt, Wct, Wht, 0 },   // text
    };

    for (int mi = 0; mi < 3; ++mi) {
        const Mod& m = mods[mi];

        // M = x^T A : [B, F, S]
        gemm_kernel<128,128,8,8,8,true,true,0><<<dim3(1, NS/128, NB), blk>>>(
            m.x, m.Amat, Mx, NS, NF, NS, NS,
            (long long)NS*NF, 0, (long long)NF*NS,
            nullptr, nullptr, 0, 0, nullptr);

        // C[:, :, 0:F]  = tanh( (M @ clo) / 16 )
        gemm_kernel<128,128,8,8,8,false,true,3><<<dim3(1, 1, NB), blk>>>(
            Mx, m.clo, Cx, NS, NS, NF, 2*NF,
            (long long)NF*NS, (long long)NS*NF, (long long)NF*2*NF,
            nullptr, nullptr, 0, 0, nullptr);
        // C[:, :, F:2F] = tanh( (M @ G) / 16 )
        gemm_kernel<128,128,8,8,8,false,true,3><<<dim3(1, 1, NB), blk>>>(
            Mx, G, Cx + NF, NS, NS, NF, 2*NF,
            (long long)NF*NS, (long long)NS*NF, (long long)NF*2*NF,
            nullptr, nullptr, 0, 0, nullptr);

        // H = C @ Wc^T   (store), then H = relu(H + x^T @ Wk^T)
        gemm_kernel<64,64,16,4,4,false,false,0><<<dim3(2, 1, NB), blk>>>(
            Cx, m.Wc, H, 2*NF, 2*NF, 2*NF, NK,
            (long long)NF*2*NF, 0, (long long)NF*NK,
            nullptr, nullptr, 0, 0, nullptr);
        gemm_kernel<64,64,16,4,4,true,false,4><<<dim3(2, 1, NB), blk>>>(
            m.x, m.Wk, H, NS, NF, NS, NK,
            (long long)NS*NF, 0, (long long)NF*NK,
            nullptr, H, NK, (long long)NF*NK, nullptr);

        // out = Wh @ H^T + x : [B, S, F]
        gemm_kernel<128,128,8,8,8,false,false,5><<<dim3(NS/128, 1, NB), blk>>>(
            m.Wh, H, out + (long long)m.slot * BSROWS * NF, NK, NK, NK, NF,
            0, (long long)NF*NK, (long long)NS*NF,
            nullptr, (float*)m.x, NF, (long long)NS*NF, nullptr);
    }
}

// round 3
// speedup vs baseline: 2.1711x; 2.1711x over previous
#include <cuda_runtime.h>
#include <math.h>
#include <stdint.h>

#define NB 64
#define NS 1024
#define NF 128
#define NK 64
#define BSROWS (NB*NS)

// ---------------- scratch ----------------
__device__ float g_p1[BSROWS*NF];
__device__ float g_p2[BSROWS*NF];
__device__ float g_G [BSROWS*NF];
__device__ float g_M [NB*NF*NS];
__device__ float g_C [NB*NF*2*NF];
__device__ float g_H [NB*NF*NK];
__device__ float g_ss[4];
__device__ float g_w [4];
__device__ float g_cn[NB*NF];

// ---------------- small kernels ----------------
__global__ void zero_kernel() {
    int i = blockIdx.x * blockDim.x + threadIdx.x;
    if (i < 4) g_ss[i] = 0.f;
    if (i < NB*NF) g_cn[i] = 0.f;
}

__global__ void scalars_kernel() {
    float n1 = sqrtf(g_ss[0]), n2 = sqrtf(g_ss[1]), n3 = sqrtf(g_ss[2]);
    g_w[0] = n1 / (n1 + n2);
    g_w[1] = n2 / (n1 + n2);
    g_w[2] = 2.f * n3 * n3 / (n1 + n2 + n3);
}

__global__ void colnorm_kernel() {
    int b = blockIdx.x, c = blockIdx.y, f = threadIdx.x;
    float w1 = g_w[0], w2 = g_w[1], cc = g_w[2];
    float s = 0.f;
    int base = (b*NS + c*32)*NF + f;
    #pragma unroll 4
    for (int i = 0; i < 32; ++i) {
        float z = w1*g_p1[base + i*NF] + w2*g_p2[base + i*NF] + cc;
        s += z*z;
    }
    atomicAdd(&g_cn[b*NF + f], s);
}

__global__ void gwrite_kernel() {
    int idx = blockIdx.x * blockDim.x + threadIdx.x;
    if (idx >= BSROWS*NF) return;
    int f = idx & (NF - 1);
    int b = idx / (NS*NF);
    float z = g_w[0]*g_p1[idx] + g_w[1]*g_p2[idx] + g_w[2];
    float n = fmaxf(sqrtf(g_cn[b*NF + f]), 1e-12f);
    g_G[idx] = z / n;
}

// ---------------- TF32 tensor-core GEMM ----------------
__device__ __forceinline__ uint32_t f2tf(float x) {
    uint32_t u;
    asm("cvt.rna.tf32.f32 %0, %1;" : "=r"(u) : "f"(x));
    return u;
}

// C[b,m,n] = sum_k Aop(b,m,k) * Bop(b,n,k)
//   TA=false: A[m*lda+k]   TA=true: A[k*lda+m]
//   TB=false: B[n*ldb+k]   TB=true: B[k*ldb+n]
// EPI: 0 store | 1 +bias,pairsum->aux,sumsq | 2 +bias,sumsq | 3 tanh(acc/16)
//      4 relu(acc+aux) | 5 acc+aux
// DB:  blockIdx.y selects Bp (y=0) or B2 (y=1); output shifted by y*BN cols.
template<int BM,int BN,int BK,int WM,int WN,bool TA,bool TB,int EPI,bool DB>
__global__ __launch_bounds__((BM/WM)*(BN/WN)*32, 512/((BM/WM)*(BN/WN)*32))
void tgemm(const float* __restrict__ A, const float* __restrict__ Bp,
           const float* __restrict__ B2,
           float* __restrict__ C, int K,
           int lda, int ldb, int ldc,
           long long bsA, long long bsB, long long bsC,
           const float* __restrict__ bias,
           float* __restrict__ aux, int ldaux, long long bsAux,
           float* __restrict__ ssum)
{
    constexpr int WROWS = BM/WM, WCOLS = BN/WN;
    constexpr int TPB = WROWS*WCOLS*32;
    constexpr int MT = WM/16, NT = WN/8;
    __shared__ uint32_t As[BK][BM+4];
    __shared__ uint32_t Bs[BK][BN+4];
    __shared__ float red[TPB/32];

    const int tid = threadIdx.x;
    const int bz  = blockIdx.z;
    const int m0  = blockIdx.x * BM;
    const int n0  = DB ? 0 : blockIdx.y * BN;
    const float* Ab = A + (long long)bz * bsA;
    const float* Bb = (DB && blockIdx.y)
                      ? (B2 + (long long)bz * bsB)
                      : (Bp + (long long)bz * bsB);

    const int lane = tid & 31, wid = tid >> 5;
    const int wr = wid / WCOLS, wc = wid % WCOLS;
    const int wmb = wr*WM, wnb = wc*WN;
    const int g = lane >> 2, t = lane & 3;

    float acc[MT][NT][4];
    #pragma unroll
    for (int mt = 0; mt < MT; ++mt)
        #pragma unroll
        for (int nt = 0; nt < NT; ++nt)
            #pragma unroll
            for (int q = 0; q < 4; ++q) acc[mt][nt][q] = 0.f;

    for (int k0 = 0; k0 < K; k0 += BK) {
        #pragma unroll
        for (int it = 0; it < (BM*BK)/TPB; ++it) {
            int idx = tid + it*TPB;
            if (TA) { int k = idx / BM, m = idx % BM;
                As[k][m] = f2tf(Ab[(long long)(k0 + k)*lda + (m0 + m)]);
            } else   { int m = idx / BK, k = idx % BK;
                As[k][m] = f2tf(Ab[(long long)(m0 + m)*lda + (k0 + k)]);
            }
        }
        #pragma unroll
        for (int it = 0; it < (BN*BK)/TPB; ++it) {
            int idx = tid + it*TPB;
            if (TB) { int k = idx / BN, n = idx % BN;
                Bs[k][n] = f2tf(Bb[(long long)(k0 + k)*ldb + (n0 + n)]);
            } else   { int n = idx / BK, k = idx % BK;
                Bs[k][n] = f2tf(Bb[(long long)(n0 + n)*ldb + (k0 + k)]);
            }
        }
        __syncthreads();
        #pragma unroll
        for (int kk = 0; kk < BK; kk += 8) {
            uint32_t af[MT][4], bf[NT][2];
            #pragma unroll
            for (int mt = 0; mt < MT; ++mt) {
                int mrow = wmb + mt*16 + g;
                af[mt][0] = As[kk + t    ][mrow];
                af[mt][1] = As[kk + t    ][mrow + 8];
                af[mt][2] = As[kk + t + 4][mrow];
                af[mt][3] = As[kk + t + 4][mrow + 8];
            }
            #pragma unroll
            for (int nt = 0; nt < NT; ++nt) {
                int ncol = wnb + nt*8 + g;
                bf[nt][0] = Bs[kk + t    ][ncol];
                bf[nt][1] = Bs[kk + t + 4][ncol];
            }
            #pragma unroll
            for (int mt = 0; mt < MT; ++mt)
                #pragma unroll
                for (int nt = 0; nt < NT; ++nt) {
                    asm volatile(
                        "mma.sync.aligned.m16n8k8.row.col.f32.tf32.tf32.f32 "
                        "{%0,%1,%2,%3}, {%4,%5,%6,%7}, {%8,%9}, {%0,%1,%2,%3};"
                        : "+f"(acc[mt][nt][0]), "+f"(acc[mt][nt][1]),
                          "+f"(acc[mt][nt][2]), "+f"(acc[mt][nt][3])
                        : "r"(af[mt][0]), "r"(af[mt][1]),
                          "r"(af[mt][2]), "r"(af[mt][3]),
                          "r"(bf[nt][0]), "r"(bf[nt][1]));
                }
        }
        __syncthreads();
    }

    // ---------------- epilogue ----------------
    if (EPI == 0 || EPI == 3) {
        float* Cb = C + (long long)bz * bsC + (DB ? (int)blockIdx.y * BN : 0);
        #pragma unroll
        for (int mt = 0; mt < MT; ++mt)
            #pragma unroll
            for (int nt = 0; nt < NT; ++nt) {
                int r0 = m0 + wmb + mt*16 + g;
                int c0 = n0 + wnb + nt*8 + 2*t;
                float v0 = acc[mt][nt][0], v1 = acc[mt][nt][1];
                float v2 = acc[mt][nt][2], v3 = acc[mt][nt][3];
                if (EPI == 3) {
                    v0 = tanhf(v0*0.0625f); v1 = tanhf(v1*0.0625f);
                    v2 = tanhf(v2*0.0625f); v3 = tanhf(v3*0.0625f);
                }
                Cb[(long long)r0*ldc + c0]       = v0;
                Cb[(long long)r0*ldc + c0 + 1]   = v1;
                Cb[(long long)(r0+8)*ldc + c0]   = v2;
                Cb[(long long)(r0+8)*ldc + c0+1] = v3;
            }
    } else if (EPI == 1 || EPI == 2) {
        float local = 0.f;
        #pragma unroll
        for (int mt = 0; mt < MT; ++mt)
            #pragma unroll
            for (int nt = 0; nt < NT; ++nt) {
                int r0 = m0 + wmb + mt*16 + g;
                int c0 = n0 + wnb + nt*8 + 2*t;
                float v0 = acc[mt][nt][0] + bias[c0];
                float v1 = acc[mt][nt][1] + bias[c0+1];
                float v2 = acc[mt][nt][2] + bias[c0];
                float v3 = acc[mt][nt][3] + bias[c0+1];
                local += v0*v0 + v1*v1 + v2*v2 + v3*v3;
                if (EPI == 1) {
                    aux[(long long)r0*ldaux + (c0>>1)]     = v0 + v1;
                    aux[(long long)(r0+8)*ldaux + (c0>>1)] = v2 + v3;
                }
            }
        #pragma unroll
        for (int o = 16; o; o >>= 1) local += __shfl_down_sync(0xffffffffu, local, o);
        if (lane == 0) red[wid] = local;
        __syncthreads();
        if (tid == 0) {
            float s = 0.f;
            #pragma unroll
            for (int i = 0; i < TPB/32; ++i) s += red[i];
            atomicAdd(ssum, s);
        }
    } else { // EPI 4 / 5
        float* Cb = C + (long long)bz * bsC;
        const float* Xb = aux + (long long)bz * bsAux;
        #pragma unroll
        for (int mt = 0; mt < MT; ++mt)
            #pragma unroll
            for (int nt = 0; nt < NT; ++nt) {
                int r0 = m0 + wmb + mt*16 + g;
                int c0 = n0 + wnb + nt*8 + 2*t;
                float v0 = acc[mt][nt][0] + Xb[(long long)r0*ldaux + c0];
                float v1 = acc[mt][nt][1] + Xb[(long long)r0*ldaux + c0+1];
                float v2 = acc[mt][nt][2] + Xb[(long long)(r0+8)*ldaux + c0];
                float v3 = acc[mt][nt][3] + Xb[(long long)(r0+8)*ldaux + c0+1];
                if (EPI == 4) {
                    v0 = fmaxf(v0, 0.f); v1 = fmaxf(v1, 0.f);
                    v2 = fmaxf(v2, 0.f); v3 = fmaxf(v3, 0.f);
                }
                Cb[(long long)r0*ldc + c0]       = v0;
                Cb[(long long)r0*ldc + c0+1]     = v1;
                Cb[(long long)(r0+8)*ldc + c0]   = v2;
                Cb[(long long)(r0+8)*ldc + c0+1] = v3;
            }
    }
}

// ---------------- launcher ----------------
extern "C" void kernel_launch(void* const* d_in, const int* in_sizes, int n_in,
                              void* d_out, int out_size)
{
    const float* txt = (const float*)d_in[0];
    const float* aud = (const float*)d_in[1];
    const float* vis = (const float*)d_in[2];
    const float* Wi  = (const float*)d_in[3];
    const float* bi  = (const float*)d_in[4];
    const float* Wq  = (const float*)d_in[5];
    const float* bq  = (const float*)d_in[6];
    const float* Wvp = (const float*)d_in[7];
    const float* bvp = (const float*)d_in[8];
    const float* Aa  = (const float*)d_in[9];
    const float* Av  = (const float*)d_in[10];
    const float* Al  = (const float*)d_in[11];
    const float* Wa  = (const float*)d_in[12];
    const float* Wv  = (const float*)d_in[13];
    const float* Wt  = (const float*)d_in[14];
    const float* Wca = (const float*)d_in[15];
    const float* Wcv = (const float*)d_in[16];
    const float* Wct = (const float*)d_in[17];
    const float* Wha = (const float*)d_in[18];
    const float* Whv = (const float*)d_in[19];
    const float* Wht = (const float*)d_in[20];
    float* out = (float*)d_out;

    float *p1, *p2, *G, *Mx, *Cx, *H, *ss;
    cudaGetSymbolAddress((void**)&p1, g_p1);
    cudaGetSymbolAddress((void**)&p2, g_p2);
    cudaGetSymbolAddress((void**)&G , g_G);
    cudaGetSymbolAddress((void**)&Mx, g_M);
    cudaGetSymbolAddress((void**)&Cx, g_C);
    cudaGetSymbolAddress((void**)&H , g_H);
    cudaGetSymbolAddress((void**)&ss, g_ss);

    zero_kernel<<<32, 256>>>();

    // ---- AMLP projections ----
    tgemm<128,128,16,64,32,false,false,1,false><<<dim3(BSROWS/128, 2, 1), 256>>>(
        txt, Wi, nullptr, nullptr, NF, NF, NF, 0, 0, 0, 0, bi, p1, NF, 0, ss + 0);
    tgemm<128,128,16,64,32,false,false,1,false><<<dim3(BSROWS/128, 2, 1), 256>>>(
        aud, Wq, nullptr, nullptr, NF, NF, NF, 0, 0, 0, 0, bq, p2, NF, 0, ss + 1);
    tgemm<128,128,16,64,32,false,false,2,false><<<dim3(BSROWS/128, 2, 1), 256>>>(
        vis, Wvp, nullptr, nullptr, NF, NF, NF, 0, 0, 0, 0, bvp, nullptr, 0, 0, ss + 2);

    scalars_kernel<<<1, 1>>>();
    colnorm_kernel<<<dim3(NB, 32, 1), NF>>>();
    gwrite_kernel<<<(BSROWS*NF)/256, 256>>>();

    // ---- per-modality pipeline ----
    struct Mod { const float* x; const float* Amat; const float* clo;
                 const float* Wk; const float* Wc; const float* Wh; int slot; };
    Mod mods[3] = {
        { aud, Aa, aud, Wa, Wca, Wha, 1 },
        { vis, Av, aud, Wv, Wcv, Whv, 2 },   // source bug: G_ag lo half = aud
        { txt, Al, txt, Wt, Wct, Wht, 0 },
    };

    for (int mi = 0; mi < 3; ++mi) {
        const Mod& m = mods[mi];

        // M = x^T A : [B, F, S]
        tgemm<128,128,16,64,32,true,true,0,false><<<dim3(1, NS/128, NB), 256>>>(
            m.x, m.Amat, nullptr, Mx, NS, NF, NS, NS,
            (long long)NS*NF, 0, (long long)NF*NS,
            nullptr, nullptr, 0, 0, nullptr);

        // C = tanh( (M @ [clo | G]) / 16 )  — dual-B: y=0 -> clo, y=1 -> G
        tgemm<128,128,16,64,32,false,true,3,true><<<dim3(1, 2, NB), 256>>>(
            Mx, m.clo, G, Cx, NS, NS, NF, 2*NF,
            (long long)NF*NS, (long long)NS*NF, (long long)NF*2*NF,
            nullptr, nullptr, 0, 0, nullptr);

        // H = C @ Wc^T ; then H = relu(H + x^T @ Wk^T)
        tgemm<128,64,16,64,32,false,false,0,false><<<dim3(1, 1, NB), 128>>>(
            Cx, m.Wc, nullptr, H, 2*NF, 2*NF, 2*NF, NK,
            (long long)NF*2*NF, 0, (long long)NF*NK,
            nullptr, nullptr, 0, 0, nullptr);
        tgemm<128,64,16,64,32,true,false,4,false><<<dim3(1, 1, NB), 128>>>(
            m.x, m.Wk, nullptr, H, NS, NF, NS, NK,
            (long long)NS*NF, 0, (long long)NF*NK,
            nullptr, H, NK, (long long)NF*NK, nullptr);

        // out = Wh @ H^T + x : [B, S, F]
        tgemm<128,128,16,64,32,false,false,5,false><<<dim3(NS/128, 1, NB), 256>>>(
            m.Wh, H, nullptr, out + (long long)m.slot * BSROWS * NF, NK, NK, NK, NF,
            0, (long long)NF*NK, (long long)NS*NF,
            nullptr, (float*)m.x, NF, (long long)NS*NF, nullptr);
    }
}

// round 5
// speedup vs baseline: 3.0169x; 1.3896x over previous
#include <cuda_runtime.h>
#include <math.h>
#include <stdint.h>

#define NB 64
#define NS 1024
#define NF 128
#define NK 64
#define BSROWS (NB*NS)

// ---------------- scratch ----------------
__device__ float g_p1[BSROWS*NF];
__device__ float g_p2[BSROWS*NF];
__device__ float g_G [BSROWS*NF];
__device__ float g_M [NB*NF*NS];
__device__ float g_C [NB*NF*2*NF];
__device__ float g_H [NB*NF*NK];
__device__ float g_ss[4];
__device__ float g_w [4];
__device__ float g_cn[NB*NF];

// ---------------- small kernels ----------------
__global__ void zero_kernel() {
    int i = blockIdx.x * blockDim.x + threadIdx.x;
    if (i < 4) g_ss[i] = 0.f;
    if (i < NB*NF) g_cn[i] = 0.f;
}

__global__ void scalars_kernel() {
    float n1 = sqrtf(g_ss[0]), n2 = sqrtf(g_ss[1]), n3 = sqrtf(g_ss[2]);
    g_w[0] = n1 / (n1 + n2);
    g_w[1] = n2 / (n1 + n2);
    g_w[2] = 2.f * n3 * n3 / (n1 + n2 + n3);
}

__global__ void colnorm_kernel() {
    int b = blockIdx.x, c = blockIdx.y, f = threadIdx.x;
    float w1 = g_w[0], w2 = g_w[1], cc = g_w[2];
    float s = 0.f;
    int base = (b*NS + c*32)*NF + f;
    #pragma unroll 4
    for (int i = 0; i < 32; ++i) {
        float z = w1*g_p1[base + i*NF] + w2*g_p2[base + i*NF] + cc;
        s += z*z;
    }
    atomicAdd(&g_cn[b*NF + f], s);
}

__global__ void gwrite_kernel() {
    int idx = blockIdx.x * blockDim.x + threadIdx.x;
    if (idx >= BSROWS*NF) return;
    int f = idx & (NF - 1);
    int b = idx / (NS*NF);
    float z = g_w[0]*g_p1[idx] + g_w[1]*g_p2[idx] + g_w[2];
    float n = fmaxf(sqrtf(g_cn[b*NF + f]), 1e-12f);
    g_G[idx] = z / n;
}

// ---------------- TF32 tensor-core GEMM (pipelined, vectorized) ----------------
__device__ __forceinline__ uint32_t f2tf(float x) {
    uint32_t u;
    asm("cvt.rna.tf32.f32 %0, %1;" : "=r"(u) : "f"(x));
    return u;
}

// C[b,m,n] = sum_k Aop(b,m,k) * Bop(b,n,k)
//   TA=false: A[m*lda+k]   TA=true: A[k*lda+m]
//   TB=false: B[n*ldb+k]   TB=true: B[k*ldb+n]
// EPI: 0 store | 1 +bias,pairsum->aux,sumsq | 2 +bias,sumsq | 3 tanh(acc/16)
//      4 relu(acc+aux) | 5 acc+aux
// DB:  blockIdx.y selects Bp (y=0) or B2 (y=1); output shifted by y*BN cols.
template<int BM,int BN,int BK,int WM,int WN,bool TA,bool TB,int EPI,bool DB>
__global__ __launch_bounds__((BM/WM)*(BN/WN)*32, 512/((BM/WM)*(BN/WN)*32))
void tgemm(const float* __restrict__ A, const float* __restrict__ Bp,
           const float* __restrict__ B2,
           float* __restrict__ C, int K,
           int lda, int ldb, int ldc,
           long long bsA, long long bsB, long long bsC,
           const float* __restrict__ bias,
           float* __restrict__ aux, int ldaux, long long bsAux,
           float* __restrict__ ssum)
{
    constexpr int WROWS = BM/WM, WCOLS = BN/WN;
    constexpr int TPB = WROWS*WCOLS*32;
    constexpr int MT = WM/16, NT = WN/8;
    constexpr int SA  = TA ? (BM+4) : (BK+4);
    constexpr int SB  = TB ? (BN+4) : (BK+4);
    constexpr int ASZ = TA ? BK*SA : BM*SA;
    constexpr int BSZ = TB ? BK*SB : BN*SB;
    constexpr int RA  = (BM*BK)/(4*TPB);   // float4 per thread for A
    constexpr int RB  = (BN*BK)/(4*TPB);

    __shared__ uint32_t sm[2*(ASZ+BSZ)];
    __shared__ float red[TPB/32];
    uint32_t* const As0 = sm;
    uint32_t* const Bs0 = sm + 2*ASZ;

    const int tid = threadIdx.x;
    const int bz  = blockIdx.z;
    const int m0  = blockIdx.x * BM;
    const int n0  = DB ? 0 : blockIdx.y * BN;
    const float* Ab = A + (long long)bz * bsA;
    const float* Bb = (DB && blockIdx.y)
                      ? (B2 + (long long)bz * bsB)
                      : (Bp + (long long)bz * bsB);

    const int lane = tid & 31, wid = tid >> 5;
    const int wr = wid / WCOLS, wc = wid % WCOLS;
    const int wmb = wr*WM, wnb = wc*WN;
    const int g = lane >> 2, t = lane & 3;

    float acc[MT][NT][4];
    #pragma unroll
    for (int mt = 0; mt < MT; ++mt)
        #pragma unroll
        for (int nt = 0; nt < NT; ++nt)
            #pragma unroll
            for (int q = 0; q < 4; ++q) acc[mt][nt][q] = 0.f;

    float4 ra[RA], rb[RB];

    // -------- loaders --------
    auto loadA = [&](int k0) {
        #pragma unroll
        for (int i = 0; i < RA; ++i) {
            int v = tid + i*TPB;
            if (TA) { int k = v / (BM/4), mq = v % (BM/4);
                ra[i] = *(const float4*)(Ab + (long long)(k0 + k)*lda + m0 + 4*mq);
            } else   { int m = v / (BK/4), kq = v % (BK/4);
                ra[i] = *(const float4*)(Ab + (long long)(m0 + m)*lda + k0 + 4*kq);
            }
        }
    };
    auto loadB = [&](int k0) {
        #pragma unroll
        for (int i = 0; i < RB; ++i) {
            int v = tid + i*TPB;
            if (TB) { int k = v / (BN/4), nq = v % (BN/4);
                rb[i] = *(const float4*)(Bb + (long long)(k0 + k)*ldb + n0 + 4*nq);
            } else   { int n = v / (BK/4), kq = v % (BK/4);
                rb[i] = *(const float4*)(Bb + (long long)(n0 + n)*ldb + k0 + 4*kq);
            }
        }
    };
    auto stsAB = [&](int buf) {
        uint32_t* Aw = As0 + buf*ASZ;
        uint32_t* Bw = Bs0 + buf*BSZ;
        #pragma unroll
        for (int i = 0; i < RA; ++i) {
            int v = tid + i*TPB;
            uint4 u = make_uint4(f2tf(ra[i].x), f2tf(ra[i].y), f2tf(ra[i].z), f2tf(ra[i].w));
            if (TA) { int k = v / (BM/4), mq = v % (BM/4);
                *(uint4*)(Aw + k*SA + 4*mq) = u;
            } else   { int m = v / (BK/4), kq = v % (BK/4);
                *(uint4*)(Aw + m*SA + 4*kq) = u;
            }
        }
        #pragma unroll
        for (int i = 0; i < RB; ++i) {
            int v = tid + i*TPB;
            uint4 u = make_uint4(f2tf(rb[i].x), f2tf(rb[i].y), f2tf(rb[i].z), f2tf(rb[i].w));
            if (TB) { int k = v / (BN/4), nq = v % (BN/4);
                *(uint4*)(Bw + k*SB + 4*nq) = u;
            } else   { int n = v / (BK/4), kq = v % (BK/4);
                *(uint4*)(Bw + n*SB + 4*kq) = u;
            }
        }
    };

    const int KT = K / BK;

    // -------- prologue --------
    loadA(0); loadB(0);
    stsAB(0);

    // -------- pipelined mainloop --------
    for (int kt = 0; kt < KT; ++kt) {
        if (kt + 1 < KT) { loadA((kt+1)*BK); loadB((kt+1)*BK); }
        __syncthreads();
        const uint32_t* Ar = As0 + (kt & 1)*ASZ;
        const uint32_t* Br = Bs0 + (kt & 1)*BSZ;
        #pragma unroll
        for (int kk = 0; kk < BK; kk += 8) {
            uint32_t af[MT][4], bf[NT][2];
            #pragma unroll
            for (int mt = 0; mt < MT; ++mt) {
                int mrow = wmb + mt*16 + g;
                if (TA) {
                    af[mt][0] = Ar[(kk + t    )*SA + mrow];
                    af[mt][1] = Ar[(kk + t    )*SA + mrow + 8];
                    af[mt][2] = Ar[(kk + t + 4)*SA + mrow];
                    af[mt][3] = Ar[(kk + t + 4)*SA + mrow + 8];
                } else {
                    af[mt][0] = Ar[(mrow    )*SA + kk + t];
                    af[mt][1] = Ar[(mrow + 8)*SA + kk + t];
                    af[mt][2] = Ar[(mrow    )*SA + kk + t + 4];
                    af[mt][3] = Ar[(mrow + 8)*SA + kk + t + 4];
                }
            }
            #pragma unroll
            for (int nt = 0; nt < NT; ++nt) {
                int ncol = wnb + nt*8 + g;
                if (TB) {
                    bf[nt][0] = Br[(kk + t    )*SB + ncol];
                    bf[nt][1] = Br[(kk + t + 4)*SB + ncol];
                } else {
                    bf[nt][0] = Br[ncol*SB + kk + t];
                    bf[nt][1] = Br[ncol*SB + kk + t + 4];
                }
            }
            #pragma unroll
            for (int mt = 0; mt < MT; ++mt)
                #pragma unroll
                for (int nt = 0; nt < NT; ++nt) {
                    asm volatile(
                        "mma.sync.aligned.m16n8k8.row.col.f32.tf32.tf32.f32 "
                        "{%0,%1,%2,%3}, {%4,%5,%6,%7}, {%8,%9}, {%0,%1,%2,%3};"
                        : "+f"(acc[mt][nt][0]), "+f"(acc[mt][nt][1]),
                          "+f"(acc[mt][nt][2]), "+f"(acc[mt][nt][3])
                        : "r"(af[mt][0]), "r"(af[mt][1]),
                          "r"(af[mt][2]), "r"(af[mt][3]),
                          "r"(bf[nt][0]), "r"(bf[nt][1]));
                }
        }
        if (kt + 1 < KT) stsAB((kt + 1) & 1);
    }

    // ---------------- epilogue ----------------
    if (EPI == 0 || EPI == 3) {
        float* Cb = C + (long long)bz * bsC + (DB ? (int)blockIdx.y * BN : 0);
        #pragma unroll
        for (int mt = 0; mt < MT; ++mt)
            #pragma unroll
            for (int nt = 0; nt < NT; ++nt) {
                int r0 = m0 + wmb + mt*16 + g;
                int c0 = n0 + wnb + nt*8 + 2*t;
                float v0 = acc[mt][nt][0], v1 = acc[mt][nt][1];
                float v2 = acc[mt][nt][2], v3 = acc[mt][nt][3];
                if (EPI == 3) {
                    v0 = tanhf(v0*0.0625f); v1 = tanhf(v1*0.0625f);
                    v2 = tanhf(v2*0.0625f); v3 = tanhf(v3*0.0625f);
                }
                Cb[(long long)r0*ldc + c0]       = v0;
                Cb[(long long)r0*ldc + c0 + 1]   = v1;
                Cb[(long long)(r0+8)*ldc + c0]   = v2;
                Cb[(long long)(r0+8)*ldc + c0+1] = v3;
            }
    } else if (EPI == 1 || EPI == 2) {
        float local = 0.f;
        #pragma unroll
        for (int mt = 0; mt < MT; ++mt)
            #pragma unroll
            for (int nt = 0; nt < NT; ++nt) {
                int r0 = m0 + wmb + mt*16 + g;
                int c0 = n0 + wnb + nt*8 + 2*t;
                float v0 = acc[mt][nt][0] + bias[c0];
                float v1 = acc[mt][nt][1] + bias[c0+1];
                float v2 = acc[mt][nt][2] + bias[c0];
                float v3 = acc[mt][nt][3] + bias[c0+1];
                local += v0*v0 + v1*v1 + v2*v2 + v3*v3;
                if (EPI == 1) {
                    aux[(long long)r0*ldaux + (c0>>1)]     = v0 + v1;
                    aux[(long long)(r0+8)*ldaux + (c0>>1)] = v2 + v3;
                }
            }
        #pragma unroll
        for (int o = 16; o; o >>= 1) local += __shfl_down_sync(0xffffffffu, local, o);
        if (lane == 0) red[wid] = local;
        __syncthreads();
        if (tid == 0) {
            float s = 0.f;
            #pragma unroll
            for (int i = 0; i < TPB/32; ++i) s += red[i];
            atomicAdd(ssum, s);
        }
    } else { // EPI 4 / 5
        float* Cb = C + (long long)bz * bsC;
        const float* Xb = aux + (long long)bz * bsAux;
        #pragma unroll
        for (int mt = 0; mt < MT; ++mt)
            #pragma unroll
            for (int nt = 0; nt < NT; ++nt) {
                int r0 = m0 + wmb + mt*16 + g;
                int c0 = n0 + wnb + nt*8 + 2*t;
                float v0 = acc[mt][nt][0] + Xb[(long long)r0*ldaux + c0];
                float v1 = acc[mt][nt][1] + Xb[(long long)r0*ldaux + c0+1];
                float v2 = acc[mt][nt][2] + Xb[(long long)(r0+8)*ldaux + c0];
                float v3 = acc[mt][nt][3] + Xb[(long long)(r0+8)*ldaux + c0+1];
                if (EPI == 4) {
                    v0 = fmaxf(v0, 0.f); v1 = fmaxf(v1, 0.f);
                    v2 = fmaxf(v2, 0.f); v3 = fmaxf(v3, 0.f);
                }
                Cb[(long long)r0*ldc + c0]       = v0;
                Cb[(long long)r0*ldc + c0+1]     = v1;
                Cb[(long long)(r0+8)*ldc + c0]   = v2;
                Cb[(long long)(r0+8)*ldc + c0+1] = v3;
            }
    }
}

// ---------------- launcher ----------------
extern "C" void kernel_launch(void* const* d_in, const int* in_sizes, int n_in,
                              void* d_out, int out_size)
{
    const float* txt = (const float*)d_in[0];
    const float* aud = (const float*)d_in[1];
    const float* vis = (const float*)d_in[2];
    const float* Wi  = (const float*)d_in[3];
    const float* bi  = (const float*)d_in[4];
    const float* Wq  = (const float*)d_in[5];
    const float* bq  = (const float*)d_in[6];
    const float* Wvp = (const float*)d_in[7];
    const float* bvp = (const float*)d_in[8];
    const float* Aa  = (const float*)d_in[9];
    const float* Av  = (const float*)d_in[10];
    const float* Al  = (const float*)d_in[11];
    const float* Wa  = (const float*)d_in[12];
    const float* Wv  = (const float*)d_in[13];
    const float* Wt  = (const float*)d_in[14];
    const float* Wca = (const float*)d_in[15];
    const float* Wcv = (const float*)d_in[16];
    const float* Wct = (const float*)d_in[17];
    const float* Wha = (const float*)d_in[18];
    const float* Whv = (const float*)d_in[19];
    const float* Wht = (const float*)d_in[20];
    float* out = (float*)d_out;

    float *p1, *p2, *G, *Mx, *Cx, *H, *ss;
    cudaGetSymbolAddress((void**)&p1, g_p1);
    cudaGetSymbolAddress((void**)&p2, g_p2);
    cudaGetSymbolAddress((void**)&G , g_G);
    cudaGetSymbolAddress((void**)&Mx, g_M);
    cudaGetSymbolAddress((void**)&Cx, g_C);
    cudaGetSymbolAddress((void**)&H , g_H);
    cudaGetSymbolAddress((void**)&ss, g_ss);

    zero_kernel<<<32, 256>>>();

    // ---- AMLP projections ----
    tgemm<128,128,16,64,32,false,false,1,false><<<dim3(BSROWS/128, 2, 1), 256>>>(
        txt, Wi, nullptr, nullptr, NF, NF, NF, 0, 0, 0, 0, bi, p1, NF, 0, ss + 0);
    tgemm<128,128,16,64,32,false,false,1,false><<<dim3(BSROWS/128, 2, 1), 256>>>(
        aud, Wq, nullptr, nullptr, NF, NF, NF, 0, 0, 0, 0, bq, p2, NF, 0, ss + 1);
    tgemm<128,128,16,64,32,false,false,2,false><<<dim3(BSROWS/128, 2, 1), 256>>>(
        vis, Wvp, nullptr, nullptr, NF, NF, NF, 0, 0, 0, 0, bvp, nullptr, 0, 0, ss + 2);

    scalars_kernel<<<1, 1>>>();
    colnorm_kernel<<<dim3(NB, 32, 1), NF>>>();
    gwrite_kernel<<<(BSROWS*NF)/256, 256>>>();

    // ---- per-modality pipeline ----
    struct Mod { const float* x; const float* Amat; const float* clo;
                 const float* Wk; const float* Wc; const float* Wh; int slot; };
    Mod mods[3] = {
        { aud, Aa, aud, Wa, Wca, Wha, 1 },
        { vis, Av, aud, Wv, Wcv, Whv, 2 },   // source bug: G_ag lo half = aud
        { txt, Al, txt, Wt, Wct, Wht, 0 },
    };

    for (int mi = 0; mi < 3; ++mi) {
        const Mod& m = mods[mi];

        // M = x^T A : [B, F, S]
        tgemm<128,128,16,64,32,true,true,0,false><<<dim3(1, NS/128, NB), 256>>>(
            m.x, m.Amat, nullptr, Mx, NS, NF, NS, NS,
            (long long)NS*NF, 0, (long long)NF*NS,
            nullptr, nullptr, 0, 0, nullptr);

        // C = tanh( (M @ [clo | G]) / 16 )  — dual-B: y=0 -> clo, y=1 -> G
        tgemm<128,128,16,64,32,false,true,3,true><<<dim3(1, 2, NB), 256>>>(
            Mx, m.clo, G, Cx, NS, NS, NF, 2*NF,
            (long long)NF*NS, (long long)NS*NF, (long long)NF*2*NF,
            nullptr, nullptr, 0, 0, nullptr);

        // H = C @ Wc^T ; then H = relu(H + x^T @ Wk^T)
        tgemm<128,64,16,64,32,false,false,0,false><<<dim3(1, 1, NB), 128>>>(
            Cx, m.Wc, nullptr, H, 2*NF, 2*NF, 2*NF, NK,
            (long long)NF*2*NF, 0, (long long)NF*NK,
            nullptr, nullptr, 0, 0, nullptr);
        tgemm<128,64,16,64,32,true,false,4,false><<<dim3(1, 1, NB), 128>>>(
            m.x, m.Wk, nullptr, H, NS, NF, NS, NK,
            (long long)NS*NF, 0, (long long)NF*NK,
            nullptr, H, NK, (long long)NF*NK, nullptr);

        // out = Wh @ H^T + x : [B, S, F]
        tgemm<128,128,16,64,32,false,false,5,false><<<dim3(NS/128, 1, NB), 256>>>(
            m.Wh, H, nullptr, out + (long long)m.slot * BSROWS * NF, NK, NK, NK, NF,
            0, (long long)NF*NK, (long long)NS*NF,
            nullptr, (float*)m.x, NF, (long long)NS*NF, nullptr);
    }
}